// round 5
// baseline (speedup 1.0000x reference)
#include <cuda_runtime.h>
#include <cstdint>

#define N_ENT   100000
#define D       128
#define NB_SCAN 49

// ---------------- scratch (static, no allocs) ----------------
__device__ float4 g_neigh4[(size_t)N_ENT * 32];
__device__ float4 g_Wsw[128 * 64];      // swizzled concat(Ws,Wn): row o = 64 16B slots
__device__ int    g_cnt[N_ENT];
__device__ int    g_start[N_ENT + 1];
__device__ int    g_head[N_ENT];
__device__ int    g_bsum[64];
__device__ int    g_boff[64];
__device__ float2 g_edge[1600000];

// ---------------- f32x2 helpers ----------------
__device__ __forceinline__ unsigned long long ffma2(unsigned long long a,
                                                    unsigned long long b,
                                                    unsigned long long c) {
    unsigned long long d;
    asm("fma.rn.f32x2 %0, %1, %2, %3;" : "=l"(d) : "l"(a), "l"(b), "l"(c));
    return d;
}
__device__ __forceinline__ void unpack2(unsigned long long v, float& x, float& y) {
    asm("mov.b64 {%0, %1}, %2;" : "=f"(x), "=f"(y) : "l"(v));
}

// ---------------- prep: zero cnt + swizzle weights ----------------
__global__ void k_prep(const float* __restrict__ Ws, const float* __restrict__ Wn, int n) {
    int i = blockIdx.x * blockDim.x + threadIdx.x;
    if (i < n) g_cnt[i] = 0;
    if (i < 128 * 64) {
        int o = i >> 6, kq = i & 63;
        float4 v = (kq < 32) ? *(const float4*)(Ws + o * 128 + kq * 4)
                             : *(const float4*)(Wn + o * 128 + (kq - 32) * 4);
        g_Wsw[o * 64 + (kq ^ (o & 7))] = v;
    }
}

// ---------------- CSR build ----------------
__global__ void k_hist(const int* __restrict__ rows, int E) {
    int i = blockIdx.x * blockDim.x + threadIdx.x;
    if (i < E) atomicAdd(&g_cnt[rows[i]], 1);
}
__global__ void k_scan1(int n) {
    __shared__ int ss[256];
    int b = blockIdx.x, t = threadIdx.x;
    int base = b * 2048 + t * 8;
    int loc[8], s = 0;
#pragma unroll
    for (int i = 0; i < 8; i++) {
        int idx = base + i;
        loc[i] = (idx < n) ? g_cnt[idx] : 0;
        s += loc[i];
    }
    ss[t] = s;
    __syncthreads();
    for (int off = 1; off < 256; off <<= 1) {
        int v = 0;
        if (t >= off) v = ss[t - off];
        __syncthreads();
        if (t >= off) ss[t] += v;
        __syncthreads();
    }
    int excl = ss[t] - s;
#pragma unroll
    for (int i = 0; i < 8; i++) {
        int idx = base + i;
        if (idx < n) g_start[idx] = excl;
        excl += loc[i];
    }
    if (t == 255) g_bsum[b] = ss[255];
}
__global__ void k_scan2(int nb) {
    if (threadIdx.x == 0) {
        int s = 0;
        for (int i = 0; i < nb; i++) { g_boff[i] = s; s += g_bsum[i]; }
    }
}
__global__ void k_scan3(int n, int E) {
    int i = blockIdx.x * blockDim.x + threadIdx.x;
    if (i < n) {
        int v = g_start[i] + g_boff[i >> 11];
        g_start[i] = v;
        g_head[i] = v;
    }
    if (i == 0) g_start[n] = E;
}
__global__ void k_scatter(const int* __restrict__ rows, const int* __restrict__ cols,
                          const float* __restrict__ vals, int E) {
    int i = blockIdx.x * blockDim.x + threadIdx.x;
    if (i < E) {
        int pos = atomicAdd(&g_head[rows[i]], 1);
        g_edge[pos] = make_float2(__int_as_float(cols[i]), vals[i]);
    }
}
__global__ void k_spmm(const float4* __restrict__ embs, int n) {
    int w = (int)((blockIdx.x * blockDim.x + threadIdx.x) >> 5);
    int lane = threadIdx.x & 31;
    if (w >= n) return;
    int s = g_start[w], t = g_start[w + 1];
    float4 acc = make_float4(0.f, 0.f, 0.f, 0.f);
    int e = s;
    for (; e + 4 <= t; e += 4) {
        float2 e0 = g_edge[e], e1 = g_edge[e + 1], e2 = g_edge[e + 2], e3 = g_edge[e + 3];
        float4 r0 = embs[(size_t)__float_as_int(e0.x) * 32 + lane];
        float4 r1 = embs[(size_t)__float_as_int(e1.x) * 32 + lane];
        float4 r2 = embs[(size_t)__float_as_int(e2.x) * 32 + lane];
        float4 r3 = embs[(size_t)__float_as_int(e3.x) * 32 + lane];
        acc.x += e0.y * r0.x + e1.y * r1.x + e2.y * r2.x + e3.y * r3.x;
        acc.y += e0.y * r0.y + e1.y * r1.y + e2.y * r2.y + e3.y * r3.y;
        acc.z += e0.y * r0.z + e1.y * r1.z + e2.y * r2.z + e3.y * r3.z;
        acc.w += e0.y * r0.w + e1.y * r1.w + e2.y * r2.w + e3.y * r3.w;
    }
    for (; e < t; e++) {
        float2 ed = g_edge[e];
        float4 r = embs[(size_t)__float_as_int(ed.x) * 32 + lane];
        acc.x += ed.y * r.x; acc.y += ed.y * r.y;
        acc.z += ed.y * r.z; acc.w += ed.y * r.w;
    }
    g_neigh4[(size_t)w * 32 + lane] = acc;
}

// ---------------- GEMM: paired-K FFMA2, split-K, 64x128 tiles ----------------
#define SM_W    512
#define SM_A    (512 + 131072)
#define SM_DYN  (512 + 131072 + 65536)
#define RSTR    132

__global__ __launch_bounds__(256, 1)
void k_gemm(const float* __restrict__ x,
            const float* __restrict__ bs,
            const float* __restrict__ bn,
            float* __restrict__ out, int N) {
    extern __shared__ char sm[];
    float* bias = (float*)sm;
    char* sW = sm + SM_W;
    char* sA = sm + SM_A;
    int tid = threadIdx.x;
    int tc = tid & 15;              // cols tc*8 .. tc*8+7
    int tr = (tid >> 4) & 7;        // rows tr*8 .. tr*8+7
    int kh = tid >> 7;              // split-K half
    int base = blockIdx.x * 64;

    if (tid < 128) bias[tid] = bs[tid] + bn[tid];
    {   // weights: straight 128KB copy (pre-swizzled)
        float4* dst = (float4*)sW;
#pragma unroll
        for (int i = 0; i < 32; i++) dst[tid + i * 256] = g_Wsw[tid + i * 256];
    }
    // A tile: 64 rows x 256 k (x | neigh), swizzled 16B slots
#pragma unroll
    for (int i = 0; i < 16; i++) {
        int idx = i * 256 + tid, r = idx >> 6, kq = idx & 63;
        int gr = base + r;
        float4 v = make_float4(0.f, 0.f, 0.f, 0.f);
        if (gr < N)
            v = (kq < 32) ? *(const float4*)(x + (size_t)gr * 128 + kq * 4)
                          : g_neigh4[(size_t)gr * 32 + (kq - 32)];
        *(float4*)(sA + r * 1024 + ((kq ^ (r & 7)) << 4)) = v;
    }
    __syncthreads();

    unsigned long long acc[8][8];
#pragma unroll
    for (int i = 0; i < 8; i++)
#pragma unroll
        for (int j = 0; j < 8; j++) acc[i][j] = 0ull;

#pragma unroll 2
    for (int it = 0; it < 32; it++) {
        uint32_t koff = (uint32_t)(kh * 32 + it) << 4;
        ulonglong2 wv[8];
#pragma unroll
        for (int j = 0; j < 8; j++) {
            int row = tc * 8 + j;
            wv[j] = *(const ulonglong2*)(sW + row * 1024 + (koff ^ ((row & 7) << 4)));
        }
#pragma unroll
        for (int i = 0; i < 8; i++) {
            int row = tr * 8 + i;
            ulonglong2 av = *(const ulonglong2*)(sA + row * 1024 + (koff ^ ((row & 7) << 4)));
#pragma unroll
            for (int j = 0; j < 8; j++) {
                acc[i][j] = ffma2(av.x, wv[j].x, acc[i][j]);
                acc[i][j] = ffma2(av.y, wv[j].y, acc[i][j]);
            }
        }
    }

    // cross-half reduction through sA region
    __syncthreads();
    float* red = (float*)sA;        // [64][RSTR]
    if (kh == 1) {
#pragma unroll
        for (int i = 0; i < 8; i++) {
            float* rp = red + (tr * 8 + i) * RSTR + tc * 8;
#pragma unroll
            for (int j = 0; j < 8; j++) {
                float lo, hi;
                unpack2(acc[i][j], lo, hi);
                rp[j] = lo + hi;
            }
        }
    }
    __syncthreads();
    if (kh == 0) {
        float bb[8];
#pragma unroll
        for (int j = 0; j < 8; j++) bb[j] = bias[tc * 8 + j];
#pragma unroll
        for (int i = 0; i < 8; i++) {
            int gr = base + tr * 8 + i;
            if (gr >= N) continue;
            const float* rp = red + (tr * 8 + i) * RSTR + tc * 8;
            float v[8];
#pragma unroll
            for (int j = 0; j < 8; j++) {
                float lo, hi;
                unpack2(acc[i][j], lo, hi);
                float t = lo + hi + rp[j] + bb[j];
                v[j] = t > 0.f ? t : 0.01f * t;
            }
            float* op = out + (size_t)gr * 128 + tc * 8;
            *(float4*)op = make_float4(v[0], v[1], v[2], v[3]);
            *(float4*)(op + 4) = make_float4(v[4], v[5], v[6], v[7]);
        }
    }
}

extern "C" void kernel_launch(void* const* d_in, const int* in_sizes, int n_in,
                              void* d_out, int out_size) {
    const float* embs = (const float*)d_in[0];
    const int*   rows = (const int*)d_in[1];
    const int*   cols = (const int*)d_in[2];
    const float* vals = (const float*)d_in[3];
    const float* Ws   = (const float*)d_in[4];
    const float* bs   = (const float*)d_in[5];
    const float* Wn   = (const float*)d_in[6];
    const float* bn   = (const float*)d_in[7];
    float* out = (float*)d_out;

    int N = in_sizes[0] / D;
    int E = in_sizes[1];

    cudaFuncSetAttribute(k_gemm, cudaFuncAttributeMaxDynamicSharedMemorySize, SM_DYN);

    k_prep<<<(N + 255) / 256, 256>>>(Ws, Wn, N);
    k_hist<<<(E + 255) / 256, 256>>>(rows, E);
    k_scan1<<<NB_SCAN, 256>>>(N);
    k_scan2<<<1, 32>>>(NB_SCAN);
    k_scan3<<<(N + 255) / 256, 256>>>(N, E);
    k_scatter<<<(E + 255) / 256, 256>>>(rows, cols, vals, E);
    k_spmm<<<(N + 7) / 8, 256>>>((const float4*)embs, N);
    k_gemm<<<(N + 63) / 64, 256, SM_DYN>>>(embs, bs, bn, out, N);
}

// round 7
// speedup vs baseline: 1.6231x; 1.6231x over previous
#include <cuda_runtime.h>
#include <cstdint>

#define N_ENT   100000
#define D       128
#define NB_SCAN 49

// ---------------- scratch (static, no allocs) ----------------
__device__ float4 g_neigh4[(size_t)N_ENT * 32];
__device__ float4 g_Wsw[128 * 64];      // o-major swizzled concat(Ws,Wn)
__device__ int    g_cnt[N_ENT];
__device__ int    g_start[N_ENT + 1];
__device__ int    g_head[N_ENT];
__device__ int    g_bsum[64];
__device__ int    g_boff[64];
__device__ float2 g_edge[1600000];

// ---------------- f32x2 helpers ----------------
__device__ __forceinline__ unsigned long long ffma2(unsigned long long a,
                                                    unsigned long long b,
                                                    unsigned long long c) {
    unsigned long long d;
    asm("fma.rn.f32x2 %0, %1, %2, %3;" : "=l"(d) : "l"(a), "l"(b), "l"(c));
    return d;
}
__device__ __forceinline__ void unpack2(unsigned long long v, float& x, float& y) {
    asm("mov.b64 {%0, %1}, %2;" : "=f"(x), "=f"(y) : "l"(v));
}

// ---------------- prep: zero cnt + swizzle weights (o-major) ----------------
// granule (o, kq): stored at slot kq ^ (o & 15); holds Wcat[o][4kq..4kq+3]
__global__ void k_prep(const float* __restrict__ Ws, const float* __restrict__ Wn, int n) {
    int i = blockIdx.x * blockDim.x + threadIdx.x;
    if (i < n) g_cnt[i] = 0;
    if (i < 128 * 64) {
        int o = i >> 6, kq = i & 63;
        float4 v = (kq < 32) ? *(const float4*)(Ws + o * 128 + kq * 4)
                             : *(const float4*)(Wn + o * 128 + (kq - 32) * 4);
        g_Wsw[o * 64 + (kq ^ (o & 15))] = v;
    }
}

// ---------------- CSR build ----------------
__global__ void k_hist(const int* __restrict__ rows, int E) {
    int i = blockIdx.x * blockDim.x + threadIdx.x;
    if (i < E) atomicAdd(&g_cnt[rows[i]], 1);
}
__global__ void k_scan1(int n) {
    __shared__ int ss[256];
    int b = blockIdx.x, t = threadIdx.x;
    int base = b * 2048 + t * 8;
    int loc[8], s = 0;
#pragma unroll
    for (int i = 0; i < 8; i++) {
        int idx = base + i;
        loc[i] = (idx < n) ? g_cnt[idx] : 0;
        s += loc[i];
    }
    ss[t] = s;
    __syncthreads();
    for (int off = 1; off < 256; off <<= 1) {
        int v = 0;
        if (t >= off) v = ss[t - off];
        __syncthreads();
        if (t >= off) ss[t] += v;
        __syncthreads();
    }
    int excl = ss[t] - s;
#pragma unroll
    for (int i = 0; i < 8; i++) {
        int idx = base + i;
        if (idx < n) g_start[idx] = excl;
        excl += loc[i];
    }
    if (t == 255) g_bsum[b] = ss[255];
}
__global__ void k_scan2(int nb) {
    __shared__ int ss[64];
    int t = threadIdx.x;   // 64 threads
    int v = (t < nb) ? g_bsum[t] : 0;
    ss[t] = v;
    __syncthreads();
    for (int off = 1; off < 64; off <<= 1) {
        int u = 0;
        if (t >= off) u = ss[t - off];
        __syncthreads();
        if (t >= off) ss[t] += u;
        __syncthreads();
    }
    if (t < nb) g_boff[t] = ss[t] - v;
}
__global__ void k_scan3(int n, int E) {
    int i = blockIdx.x * blockDim.x + threadIdx.x;
    if (i < n) {
        int v = g_start[i] + g_boff[i >> 11];
        g_start[i] = v;
        g_head[i] = v;
    }
    if (i == 0) g_start[n] = E;
}
__global__ void k_scatter(const int* __restrict__ rows, const int* __restrict__ cols,
                          const float* __restrict__ vals, int E) {
    int i = blockIdx.x * blockDim.x + threadIdx.x;
    if (i < E) {
        int pos = atomicAdd(&g_head[rows[i]], 1);
        g_edge[pos] = make_float2(__int_as_float(cols[i]), vals[i]);
    }
}
__global__ void k_spmm(const float4* __restrict__ embs, int n) {
    int w = (int)((blockIdx.x * blockDim.x + threadIdx.x) >> 5);
    int lane = threadIdx.x & 31;
    if (w >= n) return;
    int s = g_start[w], t = g_start[w + 1];
    float4 acc = make_float4(0.f, 0.f, 0.f, 0.f);
    int e = s;
    for (; e + 4 <= t; e += 4) {
        float2 e0 = g_edge[e], e1 = g_edge[e + 1], e2 = g_edge[e + 2], e3 = g_edge[e + 3];
        float4 r0 = embs[(size_t)__float_as_int(e0.x) * 32 + lane];
        float4 r1 = embs[(size_t)__float_as_int(e1.x) * 32 + lane];
        float4 r2 = embs[(size_t)__float_as_int(e2.x) * 32 + lane];
        float4 r3 = embs[(size_t)__float_as_int(e3.x) * 32 + lane];
        acc.x += e0.y * r0.x + e1.y * r1.x + e2.y * r2.x + e3.y * r3.x;
        acc.y += e0.y * r0.y + e1.y * r1.y + e2.y * r2.y + e3.y * r3.y;
        acc.z += e0.y * r0.z + e1.y * r1.z + e2.y * r2.z + e3.y * r3.z;
        acc.w += e0.y * r0.w + e1.y * r1.w + e2.y * r2.w + e3.y * r3.w;
    }
    for (; e < t; e++) {
        float2 ed = g_edge[e];
        float4 r = embs[(size_t)__float_as_int(ed.x) * 32 + lane];
        acc.x += ed.y * r.x; acc.y += ed.y * r.y;
        acc.z += ed.y * r.z; acc.w += ed.y * r.w;
    }
    g_neigh4[(size_t)w * 32 + lane] = acc;
}

// ---------------- GEMM: paired-K FFMA2, split-K, 64x128 tiles ----------------
#define SM_W    512
#define SM_A    (512 + 131072)
#define SM_DYN  (512 + 131072 + 65536)
#define RSTR    132

__global__ __launch_bounds__(256, 1)
void k_gemm(const float* __restrict__ x,
            const float* __restrict__ bs,
            const float* __restrict__ bn,
            float* __restrict__ out, int N) {
    extern __shared__ char sm[];
    float* bias = (float*)sm;
    char* sW = sm + SM_W;       // o-major: o*1024 + slot*16, slot = kq ^ (o&15)
    char* sA = sm + SM_A;       // r-major: r*1024 + kq*16
    int tid = threadIdx.x;
    int tc = tid & 15;          // cols tc + j*16
    int tr = (tid >> 4) & 7;    // rows tr*8 .. tr*8+7
    int kh = tid >> 7;          // split-K half: kq in [kh*32, kh*32+32)
    int base = blockIdx.x * 64;

    if (tid < 128) bias[tid] = bs[tid] + bn[tid];
    {   // weights: straight 128KB copy (pre-swizzled)
        float4* dst = (float4*)sW;
#pragma unroll
        for (int i = 0; i < 32; i++) dst[tid + i * 256] = g_Wsw[tid + i * 256];
    }
    // A tile: 64 rows x 64 granules (x | neigh), r-major, contiguous STS.128
#pragma unroll
    for (int i = 0; i < 16; i++) {
        int idx = i * 256 + tid, r = idx >> 6, kq = idx & 63;
        int gr = base + r;
        float4 v = make_float4(0.f, 0.f, 0.f, 0.f);
        if (gr < N)
            v = (kq < 32) ? *(const float4*)(x + (size_t)gr * 128 + kq * 4)
                          : g_neigh4[(size_t)gr * 32 + (kq - 32)];
        *(float4*)(sA + r * 1024 + (kq << 4)) = v;
    }
    __syncthreads();

    unsigned long long acc[8][8];
#pragma unroll
    for (int i = 0; i < 8; i++)
#pragma unroll
        for (int j = 0; j < 8; j++) acc[i][j] = 0ull;

#pragma unroll 2
    for (int it = 0; it < 32; it++) {
        int kq = kh * 32 + it;
        ulonglong2 wv[8];
#pragma unroll
        for (int j = 0; j < 8; j++) {
            int o = tc + j * 16;
            wv[j] = *(const ulonglong2*)(sW + o * 1024 + ((kq ^ (o & 15)) << 4));
        }
#pragma unroll
        for (int i = 0; i < 8; i++) {
            int r = tr * 8 + i;
            ulonglong2 av = *(const ulonglong2*)(sA + r * 1024 + (kq << 4));
#pragma unroll
            for (int j = 0; j < 8; j++) {
                acc[i][j] = ffma2(av.x, wv[j].x, acc[i][j]);
                acc[i][j] = ffma2(av.y, wv[j].y, acc[i][j]);
            }
        }
    }

    // cross-half reduction through sA region
    __syncthreads();
    float* red = (float*)sA;    // [64][RSTR]
    if (kh == 1) {
#pragma unroll
        for (int i = 0; i < 8; i++) {
            float* rp = red + (tr * 8 + i) * RSTR + tc * 8;
            // NOTE: this thread's cols are tc + j*16 (strided), store accordingly
            float* rp2 = red + (tr * 8 + i) * RSTR;
#pragma unroll
            for (int j = 0; j < 8; j++) {
                float lo, hi;
                unpack2(acc[i][j], lo, hi);
                rp2[tc + j * 16] = lo + hi;
            }
            (void)rp;
        }
    }
    __syncthreads();
    if (kh == 0) {
#pragma unroll
        for (int i = 0; i < 8; i++) {
            int gr = base + tr * 8 + i;
            if (gr >= N) continue;
            const float* rp = red + (tr * 8 + i) * RSTR;
            float* op = out + (size_t)gr * 128;
#pragma unroll
            for (int j = 0; j < 8; j++) {
                int c = tc + j * 16;
                float lo, hi;
                unpack2(acc[i][j], lo, hi);
                float t = lo + hi + rp[c] + bias[c];
                op[c] = t > 0.f ? t : 0.01f * t;
            }
        }
    }
}

extern "C" void kernel_launch(void* const* d_in, const int* in_sizes, int n_in,
                              void* d_out, int out_size) {
    const float* embs = (const float*)d_in[0];
    const int*   rows = (const int*)d_in[1];
    const int*   cols = (const int*)d_in[2];
    const float* vals = (const float*)d_in[3];
    const float* Ws   = (const float*)d_in[4];
    const float* bs   = (const float*)d_in[5];
    const float* Wn   = (const float*)d_in[6];
    const float* bn   = (const float*)d_in[7];
    float* out = (float*)d_out;

    int N = in_sizes[0] / D;
    int E = in_sizes[1];

    cudaFuncSetAttribute(k_gemm, cudaFuncAttributeMaxDynamicSharedMemorySize, SM_DYN);

    k_prep<<<(N + 255) / 256, 256>>>(Ws, Wn, N);
    k_hist<<<(E + 255) / 256, 256>>>(rows, E);
    k_scan1<<<NB_SCAN, 256>>>(N);
    k_scan2<<<1, 64>>>(NB_SCAN);
    k_scan3<<<(N + 255) / 256, 256>>>(N, E);
    k_scatter<<<(E + 255) / 256, 256>>>(rows, cols, vals, E);
    k_spmm<<<(N + 7) / 8, 256>>>((const float4*)embs, N);
    k_gemm<<<(N + 63) / 64, 256, SM_DYN>>>(embs, bs, bn, out, N);
}

// round 8
// speedup vs baseline: 1.8926x; 1.1660x over previous
#include <cuda_runtime.h>
#include <cstdint>

#define N_ENT   100000
#define D       128
#define NB_SCAN 49

// ---------------- scratch (static, no allocs) ----------------
__device__ float4 g_neigh4[(size_t)N_ENT * 32];
__device__ float2 g_Wd[2 * 128 * 128];   // dup-pair weights: [slab][k][c] = (W[c][k], W[c][k])
__device__ int    g_cnt[N_ENT];
__device__ int    g_start[N_ENT + 1];
__device__ int    g_head[N_ENT];
__device__ int    g_bsum[64];
__device__ int    g_boff[64];
__device__ float2 g_edge[1600000];

// ---------------- f32x2 helpers ----------------
__device__ __forceinline__ unsigned long long ffma2(unsigned long long a,
                                                    unsigned long long b,
                                                    unsigned long long c) {
    unsigned long long d;
    asm("fma.rn.f32x2 %0, %1, %2, %3;" : "=l"(d) : "l"(a), "l"(b), "l"(c));
    return d;
}
__device__ __forceinline__ void unpack2(unsigned long long v, float& x, float& y) {
    asm("mov.b64 {%0, %1}, %2;" : "=f"(x), "=f"(y) : "l"(v));
}

// ---------------- prep: zero cnt + build dup-pair weights ----------------
__global__ void k_prep(const float* __restrict__ Ws, const float* __restrict__ Wn, int n) {
    int i = blockIdx.x * blockDim.x + threadIdx.x;
    if (i < n) g_cnt[i] = 0;
    if (i < 2 * 128 * 128) {
        int slab = i >> 14, rem = i & 16383, k = rem >> 7, c = rem & 127;
        float w = (slab ? Wn : Ws)[c * 128 + k];
        g_Wd[i] = make_float2(w, w);
    }
}

// ---------------- CSR build ----------------
__global__ void k_hist(const int* __restrict__ rows, int E) {
    int i = blockIdx.x * blockDim.x + threadIdx.x;
    if (i < E) atomicAdd(&g_cnt[rows[i]], 1);
}
__global__ void k_scan1(int n) {
    __shared__ int ss[256];
    int b = blockIdx.x, t = threadIdx.x;
    int base = b * 2048 + t * 8;
    int loc[8], s = 0;
#pragma unroll
    for (int i = 0; i < 8; i++) {
        int idx = base + i;
        loc[i] = (idx < n) ? g_cnt[idx] : 0;
        s += loc[i];
    }
    ss[t] = s;
    __syncthreads();
    for (int off = 1; off < 256; off <<= 1) {
        int v = 0;
        if (t >= off) v = ss[t - off];
        __syncthreads();
        if (t >= off) ss[t] += v;
        __syncthreads();
    }
    int excl = ss[t] - s;
#pragma unroll
    for (int i = 0; i < 8; i++) {
        int idx = base + i;
        if (idx < n) g_start[idx] = excl;
        excl += loc[i];
    }
    if (t == 255) g_bsum[b] = ss[255];
}
__global__ void k_scan2(int nb) {
    __shared__ int ss[64];
    int t = threadIdx.x;
    int v = (t < nb) ? g_bsum[t] : 0;
    ss[t] = v;
    __syncthreads();
    for (int off = 1; off < 64; off <<= 1) {
        int u = 0;
        if (t >= off) u = ss[t - off];
        __syncthreads();
        if (t >= off) ss[t] += u;
        __syncthreads();
    }
    if (t < nb) g_boff[t] = ss[t] - v;
}
__global__ void k_scan3(int n, int E) {
    int i = blockIdx.x * blockDim.x + threadIdx.x;
    if (i < n) {
        int v = g_start[i] + g_boff[i >> 11];
        g_start[i] = v;
        g_head[i] = v;
    }
    if (i == 0) g_start[n] = E;
}
__global__ void k_scatter(const int* __restrict__ rows, const int* __restrict__ cols,
                          const float* __restrict__ vals, int E) {
    int i = blockIdx.x * blockDim.x + threadIdx.x;
    if (i < E) {
        int pos = atomicAdd(&g_head[rows[i]], 1);
        g_edge[pos] = make_float2(__int_as_float(cols[i]), vals[i]);
    }
}
__global__ void k_spmm(const float4* __restrict__ embs, int n) {
    int w = (int)((blockIdx.x * blockDim.x + threadIdx.x) >> 5);
    int lane = threadIdx.x & 31;
    if (w >= n) return;
    int s = g_start[w], t = g_start[w + 1];
    float4 acc = make_float4(0.f, 0.f, 0.f, 0.f);
    int e = s;
    for (; e + 4 <= t; e += 4) {
        float2 e0 = g_edge[e], e1 = g_edge[e + 1], e2 = g_edge[e + 2], e3 = g_edge[e + 3];
        float4 r0 = embs[(size_t)__float_as_int(e0.x) * 32 + lane];
        float4 r1 = embs[(size_t)__float_as_int(e1.x) * 32 + lane];
        float4 r2 = embs[(size_t)__float_as_int(e2.x) * 32 + lane];
        float4 r3 = embs[(size_t)__float_as_int(e3.x) * 32 + lane];
        acc.x += e0.y * r0.x + e1.y * r1.x + e2.y * r2.x + e3.y * r3.x;
        acc.y += e0.y * r0.y + e1.y * r1.y + e2.y * r2.y + e3.y * r3.y;
        acc.z += e0.y * r0.z + e1.y * r1.z + e2.y * r2.z + e3.y * r3.z;
        acc.w += e0.y * r0.w + e1.y * r1.w + e2.y * r2.w + e3.y * r3.w;
    }
    for (; e < t; e++) {
        float2 ed = g_edge[e];
        float4 r = embs[(size_t)__float_as_int(ed.x) * 32 + lane];
        acc.x += ed.y * r.x; acc.y += ed.y * r.y;
        acc.z += ed.y * r.z; acc.w += ed.y * r.w;
    }
    g_neigh4[(size_t)w * 32 + lane] = acc;
}

// ---------------- GEMM: row-paired FFMA2, 128x128 tiles, persistent ----------------
// self (FINAL=false): out = A@Ws^T + (bs+bn)        [A = entity_embs]
// final (FINAL=true): out = leaky(out + neigh@Wn^T) [A = g_neigh4]
#define GSM_W    512
#define GSM_A    (512 + 131072)
#define GSM_TOT  (512 + 131072 + 66560)   // 198144

template <bool FINAL>
__global__ __launch_bounds__(256, 1)
void k_gemm(const float* __restrict__ Ain,
            const float* __restrict__ bs, const float* __restrict__ bn,
            float* __restrict__ out, int N) {
    extern __shared__ char sm[];
    float* bias = (float*)sm;
    char* sW = sm + GSM_W;      // plane k: 1024B, entry c: dup pair @ c*8
    char* sA = sm + GSM_A;      // plane k: 520B,  entry r: scalar @ r*4
    const float* A = FINAL ? (const float*)g_neigh4 : Ain;
    int tid = threadIdx.x, lane = tid & 31, wid = tid >> 5;

    if (!FINAL && tid < 128) bias[tid] = bs[tid] + bn[tid];
    {   // weights: straight 128KB copy of dup-pair slab
        const float4* src = (const float4*)(g_Wd + (FINAL ? 16384 : 0));
        float4* dst = (float4*)sW;
#pragma unroll
        for (int i = 0; i < 32; i++) dst[tid + i * 256] = src[tid + i * 256];
    }

    int ntiles = (N + 127) >> 7;
    for (int tile = blockIdx.x; tile < ntiles; tile += gridDim.x) {
        int row0 = tile << 7;
        // fill sA k-major (scalar planes)
#pragma unroll
        for (int i = 0; i < 16; i++) {
            int idx = i * 256 + tid, r = idx >> 5, kq = idx & 31;
            int gr = row0 + r;
            float4 v = make_float4(0.f, 0.f, 0.f, 0.f);
            if (gr < N) v = *(const float4*)(A + (size_t)gr * 128 + kq * 4);
            char* base = sA + r * 4 + kq * 4 * 520;
            *(float*)(base)           = v.x;
            *(float*)(base + 520)     = v.y;
            *(float*)(base + 2 * 520) = v.z;
            *(float*)(base + 3 * 520) = v.w;
        }
        __syncthreads();

        // warp wid owns rows wid*16..wid*16+15 (8 row-pairs); lane owns cols lane+32j
        unsigned long long acc[8][4];
#pragma unroll
        for (int i = 0; i < 8; i++)
#pragma unroll
            for (int j = 0; j < 4; j++) acc[i][j] = 0ull;

#pragma unroll 4
        for (int k = 0; k < 128; k++) {
            const char* ak = sA + k * 520 + wid * 64;     // row-pair i @ +i*8 (broadcast)
            const char* wk = sW + k * 1024 + lane * 8;    // col j @ +j*256 (contiguous)
            unsigned long long a[8], w[4];
#pragma unroll
            for (int i = 0; i < 8; i++) a[i] = *(const unsigned long long*)(ak + i * 8);
#pragma unroll
            for (int j = 0; j < 4; j++) w[j] = *(const unsigned long long*)(wk + j * 256);
#pragma unroll
            for (int i = 0; i < 8; i++)
#pragma unroll
                for (int j = 0; j < 4; j++) acc[i][j] = ffma2(a[i], w[j], acc[i][j]);
        }
        __syncthreads();

        // stage sums to red[r][c] (row stride 512B) for coalesced output
        float* red = (float*)sA;
#pragma unroll
        for (int i = 0; i < 8; i++) {
            int r0 = (wid * 8 + i) * 2;
#pragma unroll
            for (int j = 0; j < 4; j++) {
                int c = lane + j * 32;
                float lo, hi;
                unpack2(acc[i][j], lo, hi);
                red[r0 * 128 + c] = lo;
                red[(r0 + 1) * 128 + c] = hi;
            }
        }
        __syncthreads();

        // coalesced epilogue
#pragma unroll
        for (int i = 0; i < 16; i++) {
            int idx = i * 256 + tid, r = idx >> 5, kq = idx & 31;
            int gr = row0 + r;
            if (gr < N) {
                float4 s = *(const float4*)(red + r * 128 + kq * 4);
                float* op = out + (size_t)gr * 128 + kq * 4;
                if (FINAL) {
                    float4 o = *(const float4*)op;
                    s.x += o.x; s.y += o.y; s.z += o.z; s.w += o.w;
                    s.x = s.x > 0.f ? s.x : 0.01f * s.x;
                    s.y = s.y > 0.f ? s.y : 0.01f * s.y;
                    s.z = s.z > 0.f ? s.z : 0.01f * s.z;
                    s.w = s.w > 0.f ? s.w : 0.01f * s.w;
                } else {
                    float4 b = *(const float4*)(bias + kq * 4);
                    s.x += b.x; s.y += b.y; s.z += b.z; s.w += b.w;
                }
                *(float4*)op = s;
            }
        }
        __syncthreads();
    }
}

extern "C" void kernel_launch(void* const* d_in, const int* in_sizes, int n_in,
                              void* d_out, int out_size) {
    const float* embs = (const float*)d_in[0];
    const int*   rows = (const int*)d_in[1];
    const int*   cols = (const int*)d_in[2];
    const float* vals = (const float*)d_in[3];
    const float* Ws   = (const float*)d_in[4];
    const float* bs   = (const float*)d_in[5];
    const float* Wn   = (const float*)d_in[6];
    const float* bn   = (const float*)d_in[7];
    float* out = (float*)d_out;

    int N = in_sizes[0] / D;
    int E = in_sizes[1];

    static cudaStream_t s2 = nullptr;
    static cudaEvent_t evA = nullptr, evB = nullptr;
    if (!s2) {
        cudaStreamCreateWithFlags(&s2, cudaStreamNonBlocking);
        cudaEventCreateWithFlags(&evA, cudaEventDisableTiming);
        cudaEventCreateWithFlags(&evB, cudaEventDisableTiming);
    }

    cudaFuncSetAttribute(k_gemm<false>, cudaFuncAttributeMaxDynamicSharedMemorySize, GSM_TOT);
    cudaFuncSetAttribute(k_gemm<true>,  cudaFuncAttributeMaxDynamicSharedMemorySize, GSM_TOT);

    // prep (both branches depend on it)
    k_prep<<<(N + 255) / 256, 256>>>(Ws, Wn, N);

    // fork: self-GEMM on side stream, CSR/SpMM chain on main stream
    cudaEventRecord(evA, 0);
    cudaStreamWaitEvent(s2, evA, 0);
    k_gemm<false><<<148, 256, GSM_TOT, s2>>>(embs, bs, bn, out, N);

    k_hist<<<(E + 255) / 256, 256>>>(rows, E);
    k_scan1<<<NB_SCAN, 256>>>(N);
    k_scan2<<<1, 64>>>(NB_SCAN);
    k_scan3<<<(N + 255) / 256, 256>>>(N, E);
    k_scatter<<<(E + 255) / 256, 256>>>(rows, cols, vals, E);
    k_spmm<<<(N + 7) / 8, 256>>>((const float4*)embs, N);

    // join, then final GEMM fuses add + leaky
    cudaEventRecord(evB, s2);
    cudaStreamWaitEvent(0, evB, 0);
    k_gemm<true><<<148, 256, GSM_TOT>>>(nullptr, nullptr, nullptr, out, N);
}